// round 6
// baseline (speedup 1.0000x reference)
#include <cuda_runtime.h>
#include <cuda_fp16.h>
#include <cstdint>

// Problem constants: N=100000, F_IN=512, F_OUT=128, nnz=1.6M each
#define F_OUT  128
#define F_IN   512
#define NMAX   100000
#define CAP    64      // ELL row capacity; degrees ~Poisson(16), P(deg>=64) ~ 1e-18

// ---------- scratch (__device__ globals; allocation-free) ----------
__device__ float  g_base[(size_t)NMAX * F_OUT];        // intermediate [N,128] fp32 (51.2 MB, L2-resident)
__device__ __half g_wh[(size_t)F_IN * F_OUT];          // W in fp16 (128 KB, L1-resident)
__device__ int    d_deg_f[NMAX];
__device__ int    d_deg_a[NMAX];
__device__ int2   d_ell_f[(size_t)NMAX * CAP];         // packed {col, val_bits}
__device__ int2   d_ell_a[(size_t)NMAX * CAP];         // packed {src, val_bits}

// ---------- prep: zero degree counters + convert W to fp16, one kernel ----------
__global__ void prep_kernel(const float2* __restrict__ w2, int n) {
    int stride = gridDim.x * blockDim.x;
    int t0 = blockIdx.x * blockDim.x + threadIdx.x;
    for (int i = t0; i < n; i += stride) {
        d_deg_f[i] = 0;
        d_deg_a[i] = 0;
    }
    for (int i = t0; i < (F_IN * F_OUT) / 2; i += stride) {
        float2 f = w2[i];
        reinterpret_cast<__half2*>(g_wh)[i] = __floats2half2_rn(f.x, f.y);
    }
}

__global__ void build_ell_kernel(const int* __restrict__ f_rows,
                                 const int* __restrict__ f_cols,
                                 const float* __restrict__ f_vals, int fn,
                                 const int* __restrict__ a_dst,
                                 const int* __restrict__ a_src,
                                 const float* __restrict__ a_vals, int an) {
    int i = blockIdx.x * blockDim.x + threadIdx.x;
    if (i < fn) {
        int r = f_rows[i];
        int p = atomicAdd(&d_deg_f[r], 1);
        p = min(p, CAP - 1);                           // overflow guard (never hit)
        d_ell_f[(size_t)r * CAP + p] = make_int2(f_cols[i], __float_as_int(f_vals[i]));
    } else if (i < fn + an) {
        int j = i - fn;
        int r = a_dst[j];
        int p = atomicAdd(&d_deg_a[r], 1);
        p = min(p, CAP - 1);
        d_ell_a[(size_t)r * CAP + p] = make_int2(a_src[j], __float_as_int(a_vals[j]));
    }
}

// ---------- gather SpMMs (warp per node, no atomics) ----------

// Step 1: base[node, :] = sum_j v_j * W[c_j, :]   (W fp16, 128 KB, L1-resident; fp32 acc/store)
__global__ void gemm_feat_kernel(int n) {
    int node = (blockIdx.x * blockDim.x + threadIdx.x) >> 5;
    int lane = threadIdx.x & 31;
    if (node >= n) return;
    int deg = min(d_deg_f[node], CAP);
    const int2* __restrict__ ell = &d_ell_f[(size_t)node * CAP];
    const uint2* __restrict__ wp = reinterpret_cast<const uint2*>(g_wh) + lane;

    float4 acc = make_float4(0.f, 0.f, 0.f, 0.f);
    for (int j = 0; j < deg; j++) {
        int2  t = __ldg(&ell[j]);                       // broadcast 8B
        float v = __int_as_float(t.y);
        uint2 w = __ldg(&wp[(size_t)t.x << 5]);         // 8B/lane from L1-resident fp16 W
        __half2 h0 = *reinterpret_cast<const __half2*>(&w.x);
        __half2 h1 = *reinterpret_cast<const __half2*>(&w.y);
        float2 f0 = __half22float2(h0);
        float2 f1 = __half22float2(h1);
        acc.x += v * f0.x;  acc.y += v * f0.y;
        acc.z += v * f1.x;  acc.w += v * f1.y;
    }
    reinterpret_cast<float4*>(g_base)[((size_t)node << 5) + lane] = acc;
}

// Step 2: out[node, :] = sum_e v_e * base[src_e, :]
// fp32 base: 1 LDG.128 + 4 FFMA per edge, zero converts (issue-bound kernel).
__global__ void gemm_adj_kernel(float4* __restrict__ out4, int n) {
    int node = (blockIdx.x * blockDim.x + threadIdx.x) >> 5;
    int lane = threadIdx.x & 31;
    if (node >= n) return;
    int deg = min(d_deg_a[node], CAP);
    const int2* __restrict__ ell = &d_ell_a[(size_t)node * CAP];
    const float4* __restrict__ bp = reinterpret_cast<const float4*>(g_base) + lane;

    float4 acc = make_float4(0.f, 0.f, 0.f, 0.f);
    for (int j = 0; j < deg; j++) {
        int2   t = __ldg(&ell[j]);                      // broadcast 8B
        float  v = __int_as_float(t.y);
        float4 b = __ldg(&bp[(size_t)t.x << 5]);        // 16B/lane, 512B/warp coalesced
        acc.x += v * b.x;  acc.y += v * b.y;
        acc.z += v * b.z;  acc.w += v * b.w;
    }
    out4[((size_t)node << 5) + lane] = acc;
}

// Inputs (metadata order):
//   d_in[0]: adj_indices  int32  [2 * N_EDGES]   (dst rows, then src cols)
//   d_in[1]: adj_values   fp32   [N_EDGES]
//   d_in[2]: feat_rows    int32  [FEAT_NNZ]
//   d_in[3]: feat_cols    int32  [FEAT_NNZ]
//   d_in[4]: feat_values  fp32   [FEAT_NNZ]
//   d_in[5]: weight       fp32   [F_IN * F_OUT]
//   d_in[6]: num_nodes    int32  [1]
// Output: fp32 [N, F_OUT]
extern "C" void kernel_launch(void* const* d_in, const int* in_sizes, int n_in,
                              void* d_out, int out_size) {
    const int*   adj_idx  = (const int*)  d_in[0];
    const float* adj_vals = (const float*)d_in[1];
    const int*   f_rows   = (const int*)  d_in[2];
    const int*   f_cols   = (const int*)  d_in[3];
    const float* f_vals   = (const float*)d_in[4];
    const float* weight   = (const float*)d_in[5];
    float*       out      = (float*)d_out;

    int n_edges   = in_sizes[1];
    int feat_nnz  = in_sizes[4];
    int num_nodes = out_size / F_OUT;

    prep_kernel<<<256, 512>>>((const float2*)weight, num_nodes);

    int total = feat_nnz + n_edges;
    build_ell_kernel<<<(total + 255) / 256, 256>>>(f_rows, f_cols, f_vals, feat_nnz,
                                                   adj_idx, adj_idx + n_edges, adj_vals,
                                                   n_edges);

    int warp_blocks = (num_nodes * 32 + 255) / 256;
    gemm_feat_kernel<<<warp_blocks, 256>>>(num_nodes);
    gemm_adj_kernel<<<warp_blocks, 256>>>((float4*)out, num_nodes);
}

// round 7
// speedup vs baseline: 1.2000x; 1.2000x over previous
#include <cuda_runtime.h>
#include <cuda_fp16.h>
#include <cstdint>

// Problem constants: N=100000, F_IN=512, F_OUT=128, nnz=1.6M each
#define F_OUT  128
#define F_IN   512
#define NMAX   100000
#define CAP    64      // ELL row capacity; degrees ~Poisson(16), P(deg>=64) ~ 1e-18

// ---------- scratch (__device__ globals; allocation-free) ----------
__device__ __half g_base[(size_t)NMAX * F_OUT];        // intermediate [N,128] fp16 (25.6 MB, L2-resident)
__device__ __half g_wh[(size_t)F_IN * F_OUT];          // W in fp16 (128 KB, L1-resident)
__device__ int    d_deg_f[NMAX];
__device__ int    d_deg_a[NMAX];
__device__ int2   d_ell_f[(size_t)NMAX * CAP];         // packed {col, val_bits}
__device__ int2   d_ell_a[(size_t)NMAX * CAP];         // packed {src, val_bits}

// ---------- prep: zero degree counters + convert W to fp16, one kernel ----------
__global__ void prep_kernel(const float2* __restrict__ w2, int n) {
    int stride = gridDim.x * blockDim.x;
    int t0 = blockIdx.x * blockDim.x + threadIdx.x;
    for (int i = t0; i < n; i += stride) {
        d_deg_f[i] = 0;
        d_deg_a[i] = 0;
    }
    for (int i = t0; i < (F_IN * F_OUT) / 2; i += stride) {
        float2 f = w2[i];
        reinterpret_cast<__half2*>(g_wh)[i] = __floats2half2_rn(f.x, f.y);
    }
}

__global__ void build_ell_kernel(const int* __restrict__ f_rows,
                                 const int* __restrict__ f_cols,
                                 const float* __restrict__ f_vals, int fn,
                                 const int* __restrict__ a_dst,
                                 const int* __restrict__ a_src,
                                 const float* __restrict__ a_vals, int an) {
    int i = blockIdx.x * blockDim.x + threadIdx.x;
    if (i < fn) {
        int r = f_rows[i];
        int p = atomicAdd(&d_deg_f[r], 1);
        p = min(p, CAP - 1);                           // overflow guard (never hit)
        d_ell_f[(size_t)r * CAP + p] = make_int2(f_cols[i], __float_as_int(f_vals[i]));
    } else if (i < fn + an) {
        int j = i - fn;
        int r = a_dst[j];
        int p = atomicAdd(&d_deg_a[r], 1);
        p = min(p, CAP - 1);
        d_ell_a[(size_t)r * CAP + p] = make_int2(a_src[j], __float_as_int(a_vals[j]));
    }
}

// ---------- gather SpMMs (warp per node, no atomics, 1-deep prefetch) ----------

__device__ __forceinline__ void fma_h2(float4& acc, float v, uint2 u) {
    __half2 h0 = *reinterpret_cast<const __half2*>(&u.x);
    __half2 h1 = *reinterpret_cast<const __half2*>(&u.y);
    float2 f0 = __half22float2(h0);
    float2 f1 = __half22float2(h1);
    acc.x += v * f0.x;  acc.y += v * f0.y;
    acc.z += v * f1.x;  acc.w += v * f1.y;
}

// Step 1: base[node, :] = sum_j v_j * W[c_j, :]   (W fp16, 128 KB, L1-resident)
__global__ void __launch_bounds__(256) gemm_feat_kernel(int n) {
    int node = (blockIdx.x * blockDim.x + threadIdx.x) >> 5;
    int lane = threadIdx.x & 31;
    if (node >= n) return;
    int deg = min(d_deg_f[node], CAP);
    const int2* __restrict__ ell = &d_ell_f[(size_t)node * CAP];
    const uint2* __restrict__ wp = reinterpret_cast<const uint2*>(g_wh) + lane;

    float4 acc = make_float4(0.f, 0.f, 0.f, 0.f);
    if (deg > 0) {
        int2  t = __ldg(ell);
        uint2 w = __ldg(&wp[(size_t)t.x << 5]);
        for (int j = 1; j < deg; j++) {
            int2  tn = __ldg(&ell[j]);                  // prefetch next edge
            uint2 wn = __ldg(&wp[(size_t)tn.x << 5]);
            fma_h2(acc, __int_as_float(t.y), w);        // consume current
            t = tn;  w = wn;
        }
        fma_h2(acc, __int_as_float(t.y), w);
    }
    __half2 h0 = __floats2half2_rn(acc.x, acc.y);
    __half2 h1 = __floats2half2_rn(acc.z, acc.w);
    uint2 u;
    u.x = *reinterpret_cast<unsigned*>(&h0);
    u.y = *reinterpret_cast<unsigned*>(&h1);
    reinterpret_cast<uint2*>(g_base)[((size_t)node << 5) + lane] = u;
}

// Step 2: out[node, :] = sum_e v_e * base[src_e, :]  (base 25.6 MB fp16, L2-resident)
__global__ void __launch_bounds__(256) gemm_adj_kernel(float4* __restrict__ out4, int n) {
    int node = (blockIdx.x * blockDim.x + threadIdx.x) >> 5;
    int lane = threadIdx.x & 31;
    if (node >= n) return;
    int deg = min(d_deg_a[node], CAP);
    const int2* __restrict__ ell = &d_ell_a[(size_t)node * CAP];
    const uint2* __restrict__ bp = reinterpret_cast<const uint2*>(g_base) + lane;

    float4 acc = make_float4(0.f, 0.f, 0.f, 0.f);
    if (deg > 0) {
        int2  t = __ldg(ell);
        uint2 b = __ldg(&bp[(size_t)t.x << 5]);
        for (int j = 1; j < deg; j++) {
            int2  tn = __ldg(&ell[j]);                  // prefetch next edge
            uint2 bn = __ldg(&bp[(size_t)tn.x << 5]);
            fma_h2(acc, __int_as_float(t.y), b);        // consume current
            t = tn;  b = bn;
        }
        fma_h2(acc, __int_as_float(t.y), b);
    }
    out4[((size_t)node << 5) + lane] = acc;
}

// Inputs (metadata order):
//   d_in[0]: adj_indices  int32  [2 * N_EDGES]   (dst rows, then src cols)
//   d_in[1]: adj_values   fp32   [N_EDGES]
//   d_in[2]: feat_rows    int32  [FEAT_NNZ]
//   d_in[3]: feat_cols    int32  [FEAT_NNZ]
//   d_in[4]: feat_values  fp32   [FEAT_NNZ]
//   d_in[5]: weight       fp32   [F_IN * F_OUT]
//   d_in[6]: num_nodes    int32  [1]
// Output: fp32 [N, F_OUT]
extern "C" void kernel_launch(void* const* d_in, const int* in_sizes, int n_in,
                              void* d_out, int out_size) {
    const int*   adj_idx  = (const int*)  d_in[0];
    const float* adj_vals = (const float*)d_in[1];
    const int*   f_rows   = (const int*)  d_in[2];
    const int*   f_cols   = (const int*)  d_in[3];
    const float* f_vals   = (const float*)d_in[4];
    const float* weight   = (const float*)d_in[5];
    float*       out      = (float*)d_out;

    int n_edges   = in_sizes[1];
    int feat_nnz  = in_sizes[4];
    int num_nodes = out_size / F_OUT;

    prep_kernel<<<256, 512>>>((const float2*)weight, num_nodes);

    int total = feat_nnz + n_edges;
    build_ell_kernel<<<(total + 255) / 256, 256>>>(f_rows, f_cols, f_vals, feat_nnz,
                                                   adj_idx, adj_idx + n_edges, adj_vals,
                                                   n_edges);

    int warp_blocks = (num_nodes * 32 + 255) / 256;
    gemm_feat_kernel<<<warp_blocks, 256>>>(num_nodes);
    gemm_adj_kernel<<<warp_blocks, 256>>>((float4*)out, num_nodes);
}